// round 1
// baseline (speedup 1.0000x reference)
#include <cuda_runtime.h>
#include <cstdint>

// Problem constants
#define BB    2
#define CIN   256
#define HH    56
#define WW    56
#define OUTC  256
#define KK    7
#define PADV  3
#define GRP   8
#define CG    32          // channels per group
#define HP    62          // padded H
#define WP    62          // padded W
#define NQ    (HH*WW)     // 3136 pixels per batch (q domain)
#define NP    (HP*WP)     // 3844 pixels per batch (padded domain)

// ---------------------------------------------------------------------------
// Scratch (device globals: allocation-free per harness rules)
// Layouts chosen channel-LAST for the attention stage's coalesced loads.
//   g_pad : [b][c][y][x]           (GEMM input, padded fm_t0)
//   g_q   : [b][h*W+w][o]          (channel-last)
//   g_k   : [b][y*WP+x][o]
//   g_v   : [b][y*WP+x][o]
// ---------------------------------------------------------------------------
__device__ float g_pad[BB * CIN * NP];   // 7.9 MB
__device__ float g_q  [BB * NQ  * OUTC]; // 6.4 MB
__device__ float g_k  [BB * NP  * OUTC]; // 7.9 MB
__device__ float g_v  [BB * NP  * OUTC]; // 7.9 MB

// ---------------------------------------------------------------------------
// 1) Pad kernel: g_pad[b][c][y][x] = fm_t0 with 3-halo of zeros
// ---------------------------------------------------------------------------
__global__ void pad_kernel(const float* __restrict__ fm) {
    int idx = blockIdx.x * blockDim.x + threadIdx.x;
    const int total = BB * CIN * NP;
    if (idx >= total) return;
    int x = idx % WP;
    int t = idx / WP;
    int y = t % HP;  t /= HP;
    int c = t % CIN;
    int b = t / CIN;
    float v = 0.f;
    int hy = y - PADV, wx = x - PADV;
    if (hy >= 0 && hy < HH && wx >= 0 && wx < WW)
        v = fm[((size_t)(b * 2 * CIN + c) * HH + hy) * WW + wx];   // fm_t0 = channels [0,256)
    g_pad[idx] = v;
}

// ---------------------------------------------------------------------------
// 2) GEMM-Q: g_q[(b*NQ+n)*256 + o] = sum_c w_q[o][c] * fm_t1[b][c][n]
//    BM=128 (o), BN=64 (n), BK=16; 256 threads; micro 8(m)x4(n), split-m.
//    NQ = 3136 = 49*64 exactly -> no n bounds.
// ---------------------------------------------------------------------------
__global__ __launch_bounds__(256) void gemm_q(const float* __restrict__ fm,
                                              const float* __restrict__ wq) {
    __shared__ float As[16][128];
    __shared__ float Bs[16][64];
    const int b  = blockIdx.z;
    const int o0 = blockIdx.y * 128;
    const int n0 = blockIdx.x * 64;
    const float* inp = fm + (size_t)b * (2 * CIN) * NQ + (size_t)CIN * NQ; // fm_t1
    const int t  = threadIdx.x;
    const int tx = t & 15;        // -> m
    const int ty = t >> 4;        // -> n

    float acc[4][8];
#pragma unroll
    for (int i = 0; i < 4; i++)
#pragma unroll
        for (int j = 0; j < 8; j++) acc[i][j] = 0.f;

    for (int k0 = 0; k0 < CIN; k0 += 16) {
#pragma unroll
        for (int r = 0; r < 2; r++) {
            int q  = t + r * 256;
            int m  = q & 127;
            int k4 = q >> 7;                // 0..3
            float4 a = *(const float4*)&wq[(size_t)(o0 + m) * CIN + k0 + k4 * 4];
            As[k4 * 4 + 0][m] = a.x;
            As[k4 * 4 + 1][m] = a.y;
            As[k4 * 4 + 2][m] = a.z;
            As[k4 * 4 + 3][m] = a.w;
        }
        {
            int k  = t >> 4;
            int n4 = t & 15;
            float4 bv = *(const float4*)&inp[(size_t)(k0 + k) * NQ + n0 + n4 * 4];
            *(float4*)&Bs[k][n4 * 4] = bv;
        }
        __syncthreads();
#pragma unroll
        for (int k = 0; k < 16; k++) {
            float4 b0 = *(float4*)&Bs[k][ty * 4];
            float4 a0 = *(float4*)&As[k][tx * 4];
            float4 a1 = *(float4*)&As[k][64 + tx * 4];
            float bn[4] = {b0.x, b0.y, b0.z, b0.w};
            float am[8] = {a0.x, a0.y, a0.z, a0.w, a1.x, a1.y, a1.z, a1.w};
#pragma unroll
            for (int i = 0; i < 4; i++)
#pragma unroll
                for (int j = 0; j < 8; j++) acc[i][j] += bn[i] * am[j];
        }
        __syncthreads();
    }
#pragma unroll
    for (int i = 0; i < 4; i++) {
        int n = n0 + ty * 4 + i;
        size_t base = ((size_t)b * NQ + n) * OUTC + o0;
        float4 s0 = {acc[i][0], acc[i][1], acc[i][2], acc[i][3]};
        float4 s1 = {acc[i][4], acc[i][5], acc[i][6], acc[i][7]};
        *(float4*)&g_q[base + tx * 4]      = s0;
        *(float4*)&g_q[base + 64 + tx * 4] = s1;
    }
}

// ---------------------------------------------------------------------------
// 3) Fused GEMM-KV: shares the B (input) tile between w_k and w_v products.
//    N = 3844 (61 tiles of 64, last partial).
// ---------------------------------------------------------------------------
__global__ __launch_bounds__(256) void gemm_kv(const float* __restrict__ wk,
                                               const float* __restrict__ wv) {
    __shared__ float Ak[16][128];
    __shared__ float Av[16][128];
    __shared__ float Bs[16][64];
    const int b  = blockIdx.z;
    const int o0 = blockIdx.y * 128;
    const int n0 = blockIdx.x * 64;
    const float* inp = g_pad + (size_t)b * CIN * NP;
    const int t  = threadIdx.x;
    const int tx = t & 15;
    const int ty = t >> 4;

    float ck[4][8], cv[4][8];
#pragma unroll
    for (int i = 0; i < 4; i++)
#pragma unroll
        for (int j = 0; j < 8; j++) { ck[i][j] = 0.f; cv[i][j] = 0.f; }

    for (int k0 = 0; k0 < CIN; k0 += 16) {
#pragma unroll
        for (int r = 0; r < 2; r++) {
            int q  = t + r * 256;
            int m  = q & 127;
            int k4 = q >> 7;
            float4 a = *(const float4*)&wk[(size_t)(o0 + m) * CIN + k0 + k4 * 4];
            Ak[k4 * 4 + 0][m] = a.x;
            Ak[k4 * 4 + 1][m] = a.y;
            Ak[k4 * 4 + 2][m] = a.z;
            Ak[k4 * 4 + 3][m] = a.w;
            float4 c = *(const float4*)&wv[(size_t)(o0 + m) * CIN + k0 + k4 * 4];
            Av[k4 * 4 + 0][m] = c.x;
            Av[k4 * 4 + 1][m] = c.y;
            Av[k4 * 4 + 2][m] = c.z;
            Av[k4 * 4 + 3][m] = c.w;
        }
        {
            int k  = t >> 4;
            int n4 = t & 15;
            int n  = n0 + n4 * 4;
            float4 bv = make_float4(0.f, 0.f, 0.f, 0.f);
            if (n < NP)   // NP = 3844 is a multiple of 4 -> float4 fully in or out
                bv = *(const float4*)&inp[(size_t)(k0 + k) * NP + n];
            *(float4*)&Bs[k][n4 * 4] = bv;
        }
        __syncthreads();
#pragma unroll
        for (int k = 0; k < 16; k++) {
            float4 b0  = *(float4*)&Bs[k][ty * 4];
            float4 k0v = *(float4*)&Ak[k][tx * 4];
            float4 k1v = *(float4*)&Ak[k][64 + tx * 4];
            float4 v0v = *(float4*)&Av[k][tx * 4];
            float4 v1v = *(float4*)&Av[k][64 + tx * 4];
            float bn[4]  = {b0.x, b0.y, b0.z, b0.w};
            float akm[8] = {k0v.x, k0v.y, k0v.z, k0v.w, k1v.x, k1v.y, k1v.z, k1v.w};
            float avm[8] = {v0v.x, v0v.y, v0v.z, v0v.w, v1v.x, v1v.y, v1v.z, v1v.w};
#pragma unroll
            for (int i = 0; i < 4; i++)
#pragma unroll
                for (int j = 0; j < 8; j++) {
                    ck[i][j] += bn[i] * akm[j];
                    cv[i][j] += bn[i] * avm[j];
                }
        }
        __syncthreads();
    }
#pragma unroll
    for (int i = 0; i < 4; i++) {
        int n = n0 + ty * 4 + i;
        if (n >= NP) continue;
        size_t base = ((size_t)b * NP + n) * OUTC + o0;
        float4 s;
        s = make_float4(ck[i][0], ck[i][1], ck[i][2], ck[i][3]);
        *(float4*)&g_k[base + tx * 4] = s;
        s = make_float4(ck[i][4], ck[i][5], ck[i][6], ck[i][7]);
        *(float4*)&g_k[base + 64 + tx * 4] = s;
        s = make_float4(cv[i][0], cv[i][1], cv[i][2], cv[i][3]);
        *(float4*)&g_v[base + tx * 4] = s;
        s = make_float4(cv[i][4], cv[i][5], cv[i][6], cv[i][7]);
        *(float4*)&g_v[base + 64 + tx * 4] = s;
    }
}

// ---------------------------------------------------------------------------
// 4) Attention: one block = (b, g, 8x8 output tile). 64 threads, 1 thread/pixel.
//    SMEM: K and V halo tiles, float4-packed [c4][pixel], row stride 197
//    (197 % 8 == 5 -> 16B-granule bank groups distinct across c4 -> no STS
//    conflicts; hot loads sweep pixel index -> conflict-free).
//    Bias is rank-1: only 7 dot-products db[0..6] per pixel.
// ---------------------------------------------------------------------------
#define TPIX   14                       // halo tile edge (8 + K-1)
#define NPIX   (TPIX*TPIX)              // 196
#define SSTR   197                      // padded pixel stride (float4 units)
#define ATTN_SMEM (2 * 8 * SSTR * 16 + CG * KK * 4)   // 50432 + 896 = 51328 B

__global__ __launch_bounds__(64) void attn_kernel(const float* __restrict__ relh,
                                                  const float* __restrict__ relw,
                                                  float* __restrict__ out) {
    extern __shared__ float4 smbuf[];
    float4* ks   = smbuf;                    // [8][SSTR]
    float4* vs   = smbuf + 8 * SSTR;         // [8][SSTR]
    float*  bias = (float*)(smbuf + 16 * SSTR);  // [32][7]

    const int b    = blockIdx.z;
    const int g    = blockIdx.y;
    const int tile = blockIdx.x;             // 0..48
    const int ty0  = (tile / 7) * 8;         // output-tile origin (also padded-coord origin)
    const int tx0  = (tile % 7) * 8;
    const int t    = threadIdx.x;

    // bias slice for this group (32 channels x 7)
    const float* rel = (g < 4) ? (relh + (size_t)g * CG * KK)
                               : (relw + (size_t)(g - 4) * CG * KK);
    for (int i = t; i < CG * KK; i += 64) bias[i] = rel[i];

    // halo tiles of K and V: 14x14 pixels x 32 channels (8 float4 per pixel)
    for (int idx = t; idx < NPIX * 8; idx += 64) {
        int c4 = idx & 7;
        int p  = idx >> 3;
        int py = p / TPIX, px = p - py * TPIX;
        size_t gbase = (((size_t)b * HP + (ty0 + py)) * WP + (tx0 + px)) * OUTC + g * CG;
        ks[c4 * SSTR + p] = *((const float4*)&g_k[gbase] + c4);
        vs[c4 * SSTR + p] = *((const float4*)&g_v[gbase] + c4);
    }
    __syncthreads();

    const int lty = t >> 3, ltx = t & 7;     // pixel within 8x8 tile
    const int h = ty0 + lty, w = tx0 + ltx;
    const int pbase = lty * TPIX + ltx;

    // q vector (32 floats) into registers
    float qf[CG];
    {
        const float4* qp = (const float4*)&g_q[((size_t)b * NQ + h * WW + w) * OUTC + g * CG];
#pragma unroll
        for (int c4 = 0; c4 < 8; c4++) {
            float4 v = qp[c4];
            qf[c4 * 4 + 0] = v.x; qf[c4 * 4 + 1] = v.y;
            qf[c4 * 4 + 2] = v.z; qf[c4 * 4 + 3] = v.w;
        }
    }

    // bias dots: db[i] = sum_c q[c] * bias[c][i]
    float db[KK];
#pragma unroll
    for (int i = 0; i < KK; i++) {
        float s = 0.f;
#pragma unroll
        for (int c = 0; c < CG; c++) s += qf[c] * bias[c * KK + i];
        db[i] = s;
    }

    // pass 1: 49 logits
    float lg[KK * KK];
#pragma unroll
    for (int n = 0; n < KK * KK; n++) {
        const int i = n / KK, j = n % KK;
        const int p = pbase + i * TPIX + j;
        float s = 0.f;
#pragma unroll
        for (int c4 = 0; c4 < 8; c4++) {
            float4 kv = ks[c4 * SSTR + p];
            s += qf[c4 * 4 + 0] * kv.x + qf[c4 * 4 + 1] * kv.y
               + qf[c4 * 4 + 2] * kv.z + qf[c4 * 4 + 3] * kv.w;
        }
        lg[n] = s + ((g < 4) ? db[i] : db[j]);
    }

    // softmax over 49
    float mx = lg[0];
#pragma unroll
    for (int n = 1; n < KK * KK; n++) mx = fmaxf(mx, lg[n]);
    float sum = 0.f;
#pragma unroll
    for (int n = 0; n < KK * KK; n++) { lg[n] = __expf(lg[n] - mx); sum += lg[n]; }
    float inv = 1.f / sum;
#pragma unroll
    for (int n = 0; n < KK * KK; n++) lg[n] *= inv;

    // pass 2: out[c] = sum_n w[n] * v[c][n];  output layout [b][o][h][w]
#pragma unroll
    for (int c4 = 0; c4 < 8; c4++) {
        float4 acc = make_float4(0.f, 0.f, 0.f, 0.f);
#pragma unroll
        for (int n = 0; n < KK * KK; n++) {
            const int p = pbase + (n / KK) * TPIX + (n % KK);
            float4 vv = vs[c4 * SSTR + p];
            acc.x += lg[n] * vv.x;
            acc.y += lg[n] * vv.y;
            acc.z += lg[n] * vv.z;
            acc.w += lg[n] * vv.w;
        }
        size_t base = ((size_t)(b * OUTC + g * CG + c4 * 4)) * NQ + h * WW + w;
        out[base]           = acc.x;
        out[base + NQ]      = acc.y;
        out[base + 2 * NQ]  = acc.z;
        out[base + 3 * NQ]  = acc.w;
    }
}

// ---------------------------------------------------------------------------
// Launch
// ---------------------------------------------------------------------------
extern "C" void kernel_launch(void* const* d_in, const int* in_sizes, int n_in,
                              void* d_out, int out_size) {
    const float* fm = (const float*)d_in[0];
    const float* wq = (const float*)d_in[1];
    const float* wk = (const float*)d_in[2];
    const float* wv = (const float*)d_in[3];
    const float* rh = (const float*)d_in[4];
    const float* rw = (const float*)d_in[5];
    float* out = (float*)d_out;

    cudaFuncSetAttribute(attn_kernel, cudaFuncAttributeMaxDynamicSharedMemorySize, ATTN_SMEM);

    {
        const int total = BB * CIN * NP;
        pad_kernel<<<(total + 255) / 256, 256>>>(fm);
    }
    gemm_q <<<dim3(NQ / 64, OUTC / 128, BB), 256>>>(fm, wq);
    gemm_kv<<<dim3((NP + 63) / 64, OUTC / 128, BB), 256>>>(wk, wv);
    attn_kernel<<<dim3(49, GRP, BB), 64, ATTN_SMEM>>>(rh, rw, out);
}